// round 1
// baseline (speedup 1.0000x reference)
#include <cuda_runtime.h>
#include <math.h>

#define T_STEPS 32
#define N_BATCH 16
#define D_DIM   256
#define A_DIM   256
#define F1_DIM  512
#define F2_DIM  256

// Scratch (allocation-free rule: __device__ globals)
__device__ float g_s2[T_STEPS * N_BATCH * D_DIM];   // [T,N,D]   512KB
__device__ float g_h1[T_STEPS * N_BATCH * F1_DIM];  // [T,N,F1]  1MB
__device__ float g_h2[T_STEPS * N_BATCH * F2_DIM];  // [T,N,F2]  512KB

// ---------------------------------------------------------------------------
// K1: fused SDC-linear + exp-filter + LIF + synapse-filter + pool + s2-LIF.
// block = (n,d) pair (4096 blocks), thread = a (256 threads).
// All per-(n,d,a) state lives in registers across the t loop.
// ---------------------------------------------------------------------------
__global__ void __launch_bounds__(256) k_snn_core(
    const float* __restrict__ x,      // [T,N,2,D]
    const float* __restrict__ W_sdc,  // [2,A]
    const float* __restrict__ b_sdc,  // [A]
    const float* __restrict__ w_syn,  // [1]
    const float* __restrict__ W_pool, // [A,1]
    const float* __restrict__ b_pool) // [1]
{
    const int a    = threadIdx.x;
    const int nd   = blockIdx.x;
    const int n    = nd >> 8;   // D = 256
    const int d    = nd & 255;
    const int lane = a & 31;
    const int warp = a >> 5;

    const float w0 = W_sdc[a];
    const float w1 = W_sdc[A_DIM + a];
    const float ba = b_sdc[a];
    const float wp = W_pool[a];
    const float ws = w_syn[0];
    const float dsyn = 1.0f - 1.0f / (1.0f + expf(-ws));  // synapse decay (=0.9)
    const float bp = b_pool[0];

    float i_s = 0.0f;  // SDC exponential synaptic current
    float v   = 0.0f;  // LIF-1 membrane
    float syn = 0.0f;  // synapse filter state
    float v2  = 0.0f;  // LIF-2 membrane (only thread 0's copy is used)

    __shared__ float sh[8];

    for (int t = 0; t < T_STEPS; ++t) {
        // x[t,n,0,d] and x[t,n,1,d]: same address for all threads -> broadcast
        const float x0 = x[((t * N_BATCH + n) * 2 + 0) * D_DIM + d];
        const float x1 = x[((t * N_BATCH + n) * 2 + 1) * D_DIM + d];
        const float h  = fmaf(x0, w0, fmaf(x1, w1, ba));

        // exp_filter decay 0.5 (tau_sdc = 2)
        i_s = fmaf(i_s, 0.5f, h);
        // LIF: v = v + (i - v)/2 ; spike at v >= 1 ; hard reset to 0
        v = fmaf(i_s - v, 0.5f, v);
        const float s1 = (v >= 1.0f) ? 1.0f : 0.0f;
        v = (s1 != 0.0f) ? 0.0f : v;
        // synapse filter
        syn = fmaf(syn, dsyn, s1);

        // block reduction of syn * W_pool[a]
        float val = syn * wp;
        #pragma unroll
        for (int off = 16; off; off >>= 1)
            val += __shfl_down_sync(0xffffffffu, val, off);
        if (lane == 0) sh[warp] = val;
        __syncthreads();
        if (warp == 0) {
            float z = (lane < 8) ? sh[lane] : 0.0f;
            #pragma unroll
            for (int off = 4; off; off >>= 1)
                z += __shfl_down_sync(0xffffffffu, z, off);
            if (lane == 0) {
                z += bp;
                // LIF-2 on z
                v2 = fmaf(z - v2, 0.5f, v2);
                const float s2 = (v2 >= 1.0f) ? 1.0f : 0.0f;
                v2 = (s2 != 0.0f) ? 0.0f : v2;
                g_s2[(t * N_BATCH + n) * D_DIM + d] = s2;
            }
        }
        __syncthreads();
    }
}

// ---------------------------------------------------------------------------
// Generic tiled SGEMM + bias: C[M,N] = A[M,K] @ B[K,N] + bias[N]
// All dims multiples of 32.
// ---------------------------------------------------------------------------
__global__ void __launch_bounds__(1024) k_gemm_bias(
    const float* __restrict__ Am, const float* __restrict__ Bm,
    const float* __restrict__ bias, float* __restrict__ C,
    int M, int K, int N)
{
    __shared__ float As[32][33];
    __shared__ float Bs[32][33];
    const int tx = threadIdx.x, ty = threadIdx.y;
    const int row = blockIdx.y * 32 + ty;
    const int col = blockIdx.x * 32 + tx;
    float acc = 0.0f;
    for (int k0 = 0; k0 < K; k0 += 32) {
        As[ty][tx] = Am[row * K + k0 + tx];
        Bs[ty][tx] = Bm[(k0 + ty) * N + col];
        __syncthreads();
        #pragma unroll
        for (int kk = 0; kk < 32; ++kk)
            acc = fmaf(As[ty][kk], Bs[kk][tx], acc);
        __syncthreads();
    }
    C[row * N + col] = acc + bias[col];
}

// ---------------------------------------------------------------------------
// Elementwise LIF scan over t, in place. buf is [T, M].
// ---------------------------------------------------------------------------
__global__ void k_lif_scan(float* __restrict__ buf, int M)
{
    const int j = blockIdx.x * blockDim.x + threadIdx.x;
    if (j >= M) return;
    float v = 0.0f;
    #pragma unroll
    for (int t = 0; t < T_STEPS; ++t) {
        const float xx = buf[t * M + j];
        v = fmaf(xx - v, 0.5f, v);
        const float s = (v >= 1.0f) ? 1.0f : 0.0f;
        buf[t * M + j] = s;
        v = (s != 0.0f) ? 0.0f : v;
    }
}

// ---------------------------------------------------------------------------
// Head: o[t,n] = h2[t,n,:] . W_out + b_out ; out[t,n] = cumsum_t o
// block = n (16 blocks), thread = g (256)
// ---------------------------------------------------------------------------
__global__ void __launch_bounds__(256) k_head(
    const float* __restrict__ W_out, const float* __restrict__ b_out,
    float* __restrict__ out)
{
    const int n = blockIdx.x;
    const int g = threadIdx.x;
    const int lane = g & 31;
    const int warp = g >> 5;
    const float w  = W_out[g];
    const float bo = b_out[0];
    __shared__ float sh[8];
    float acc = 0.0f;  // cumulative membrane (thread 0)

    for (int t = 0; t < T_STEPS; ++t) {
        float val = g_h2[(t * N_BATCH + n) * F2_DIM + g] * w;
        #pragma unroll
        for (int off = 16; off; off >>= 1)
            val += __shfl_down_sync(0xffffffffu, val, off);
        if (lane == 0) sh[warp] = val;
        __syncthreads();
        if (warp == 0) {
            float z = (lane < 8) ? sh[lane] : 0.0f;
            #pragma unroll
            for (int off = 4; off; off >>= 1)
                z += __shfl_down_sync(0xffffffffu, z, off);
            if (lane == 0) {
                acc += z + bo;
                out[t * N_BATCH + n] = acc;
            }
        }
        __syncthreads();
    }
}

extern "C" void kernel_launch(void* const* d_in, const int* in_sizes, int n_in,
                              void* d_out, int out_size)
{
    const float* x      = (const float*)d_in[0];
    const float* W_sdc  = (const float*)d_in[1];
    const float* b_sdc  = (const float*)d_in[2];
    const float* w_syn  = (const float*)d_in[3];
    const float* W_pool = (const float*)d_in[4];
    const float* b_pool = (const float*)d_in[5];
    const float* W_f1   = (const float*)d_in[6];
    const float* b_f1   = (const float*)d_in[7];
    const float* W_f2   = (const float*)d_in[8];
    const float* b_f2   = (const float*)d_in[9];
    const float* W_out  = (const float*)d_in[10];
    const float* b_out  = (const float*)d_in[11];
    float* out = (float*)d_out;

    float* s2 = nullptr; float* h1 = nullptr; float* h2 = nullptr;
    cudaGetSymbolAddress((void**)&s2, g_s2);
    cudaGetSymbolAddress((void**)&h1, g_h1);
    cudaGetSymbolAddress((void**)&h2, g_h2);

    // K1: fused SNN core -> g_s2 [T,N,D]
    k_snn_core<<<N_BATCH * D_DIM, 256>>>(x, W_sdc, b_sdc, w_syn, W_pool, b_pool);

    // K2: h1pre = s2 @ W_f1 + b_f1   (M=T*N=512, K=256, N=512)
    {
        dim3 grid(F1_DIM / 32, (T_STEPS * N_BATCH) / 32);
        dim3 blk(32, 32);
        k_gemm_bias<<<grid, blk>>>(s2, W_f1, b_f1, h1,
                                   T_STEPS * N_BATCH, D_DIM, F1_DIM);
    }
    // K3: LIF scan over t on h1 (in place), M = N*F1 = 8192
    k_lif_scan<<<(N_BATCH * F1_DIM) / 256, 256>>>(h1, N_BATCH * F1_DIM);

    // K4: h2pre = h1 @ W_f2 + b_f2   (M=512, K=512, N=256)
    {
        dim3 grid(F2_DIM / 32, (T_STEPS * N_BATCH) / 32);
        dim3 blk(32, 32);
        k_gemm_bias<<<grid, blk>>>(h1, W_f2, b_f2, h2,
                                   T_STEPS * N_BATCH, F1_DIM, F2_DIM);
    }
    // K5: LIF scan on h2, M = N*F2 = 4096
    k_lif_scan<<<(N_BATCH * F2_DIM) / 256, 256>>>(h2, N_BATCH * F2_DIM);

    // K6: readout dot + cumsum
    k_head<<<N_BATCH, 256>>>(W_out, b_out, out);
}

// round 2
// speedup vs baseline: 1.4161x; 1.4161x over previous
#include <cuda_runtime.h>
#include <math.h>

#define T_STEPS 32
#define N_BATCH 16
#define D_DIM   256
#define A_DIM   256
#define F1_DIM  512
#define F2_DIM  256
#define BK 16

// Scratch (allocation-free rule: __device__ globals)
__device__ float g_s2[T_STEPS * N_BATCH * D_DIM];   // [T,N,D]   512KB
__device__ float g_h1[T_STEPS * N_BATCH * F1_DIM];  // [T,N,F1]  1MB
__device__ float g_h2[T_STEPS * N_BATCH * F2_DIM];  // [T,N,F2]  512KB

// ---------------------------------------------------------------------------
// K1: fused SDC-linear + exp-filter + LIF + synapse-filter + pool + s2-LIF.
// block = (n,d) pair (4096 blocks), thread = a (256 threads).
// Barrier-light: per-t warp reductions -> smem; ONE __syncthreads at the end;
// warp 0 finishes the pooled sum + sequential LIF-2 chain.
// ---------------------------------------------------------------------------
__global__ void __launch_bounds__(256) k_snn_core(
    const float* __restrict__ x,      // [T,N,2,D]
    const float* __restrict__ W_sdc,  // [2,A]
    const float* __restrict__ b_sdc,  // [A]
    const float* __restrict__ w_syn,  // [1]
    const float* __restrict__ W_pool, // [A,1]
    const float* __restrict__ b_pool) // [1]
{
    const int a    = threadIdx.x;
    const int nd   = blockIdx.x;
    const int n    = nd >> 8;   // D = 256
    const int d    = nd & 255;
    const int lane = a & 31;
    const int warp = a >> 5;

    const float w0 = W_sdc[a];
    const float w1 = W_sdc[A_DIM + a];
    const float ba = b_sdc[a];
    const float wp = W_pool[a];
    const float ws = w_syn[0];
    const float dsyn = 1.0f - 1.0f / (1.0f + expf(-ws));
    const float bp = b_pool[0];

    float i_s = 0.0f;  // SDC exponential synaptic current
    float v   = 0.0f;  // LIF-1 membrane
    float syn = 0.0f;  // synapse filter state

    __shared__ float sh[T_STEPS][8];

    #pragma unroll 4
    for (int t = 0; t < T_STEPS; ++t) {
        const float x0 = x[((t * N_BATCH + n) * 2 + 0) * D_DIM + d];
        const float x1 = x[((t * N_BATCH + n) * 2 + 1) * D_DIM + d];
        const float h  = fmaf(x0, w0, fmaf(x1, w1, ba));

        i_s = fmaf(i_s, 0.5f, h);                     // exp_filter decay 0.5
        v = fmaf(i_s - v, 0.5f, v);                   // LIF tau=2
        const float s1 = (v >= 1.0f) ? 1.0f : 0.0f;
        v = (s1 != 0.0f) ? 0.0f : v;
        syn = fmaf(syn, dsyn, s1);                    // synapse filter

        float val = syn * wp;
        #pragma unroll
        for (int off = 16; off; off >>= 1)
            val += __shfl_down_sync(0xffffffffu, val, off);
        if (lane == 0) sh[t][warp] = val;
    }
    __syncthreads();

    if (warp == 0) {
        // lane == t
        float z = bp;
        #pragma unroll
        for (int w = 0; w < 8; ++w) z += sh[lane][w];

        float v2 = 0.0f, s_mine = 0.0f;
        #pragma unroll
        for (int t = 0; t < T_STEPS; ++t) {
            const float zt = __shfl_sync(0xffffffffu, z, t);
            v2 = fmaf(zt - v2, 0.5f, v2);
            const float s = (v2 >= 1.0f) ? 1.0f : 0.0f;
            v2 = (s != 0.0f) ? 0.0f : v2;
            if (lane == t) s_mine = s;
        }
        g_s2[(lane * N_BATCH + n) * D_DIM + d] = s_mine;
    }
}

// ---------------------------------------------------------------------------
// Register-tiled SGEMM + bias: C[M,N] = A[M,K] @ B[K,N] + bias[N]
// Tile 32(M) x 64(N), BK=16, 128 threads, 4x4 micro-tile per thread.
// As stored k-major so the 4-row operand read is one LDS.128.
// Requires M%32==0, N%64==0, K%16==0 (true here).
// ---------------------------------------------------------------------------
__global__ void __launch_bounds__(128) k_gemm_bias(
    const float* __restrict__ A, const float* __restrict__ B,
    const float* __restrict__ bias, float* __restrict__ C,
    int M, int K, int N)
{
    __shared__ float As[BK][32];   // [k][m]
    __shared__ float Bs[BK][64];   // [k][n]
    const int tid = threadIdx.x;
    const int tx  = tid & 15;      // col group (of 4)
    const int ty  = tid >> 4;      // row group (of 4), 0..7
    const int row0 = blockIdx.y * 32;
    const int col0 = blockIdx.x * 64;

    const int alr = tid >> 2;            // 0..31 : A row in tile
    const int alk = (tid & 3) << 2;      // 0,4,8,12 : A k-seg
    const int brr = tid >> 4;            // 0..7  : B k row
    const int bcc = (tid & 15) << 2;     // B col

    float acc[4][4] = {};

    for (int k0 = 0; k0 < K; k0 += BK) {
        const float4 av  = *(const float4*)(A + (row0 + alr) * K + k0 + alk);
        const float4 bv0 = *(const float4*)(B + (k0 + brr    ) * N + col0 + bcc);
        const float4 bv1 = *(const float4*)(B + (k0 + brr + 8) * N + col0 + bcc);
        As[alk + 0][alr] = av.x;
        As[alk + 1][alr] = av.y;
        As[alk + 2][alr] = av.z;
        As[alk + 3][alr] = av.w;
        *(float4*)(&Bs[brr][bcc])     = bv0;
        *(float4*)(&Bs[brr + 8][bcc]) = bv1;
        __syncthreads();
        #pragma unroll
        for (int kk = 0; kk < BK; ++kk) {
            const float4 a = *(const float4*)(&As[kk][ty << 2]);
            const float4 b = *(const float4*)(&Bs[kk][tx << 2]);
            acc[0][0] = fmaf(a.x, b.x, acc[0][0]);
            acc[0][1] = fmaf(a.x, b.y, acc[0][1]);
            acc[0][2] = fmaf(a.x, b.z, acc[0][2]);
            acc[0][3] = fmaf(a.x, b.w, acc[0][3]);
            acc[1][0] = fmaf(a.y, b.x, acc[1][0]);
            acc[1][1] = fmaf(a.y, b.y, acc[1][1]);
            acc[1][2] = fmaf(a.y, b.z, acc[1][2]);
            acc[1][3] = fmaf(a.y, b.w, acc[1][3]);
            acc[2][0] = fmaf(a.z, b.x, acc[2][0]);
            acc[2][1] = fmaf(a.z, b.y, acc[2][1]);
            acc[2][2] = fmaf(a.z, b.z, acc[2][2]);
            acc[2][3] = fmaf(a.z, b.w, acc[2][3]);
            acc[3][0] = fmaf(a.w, b.x, acc[3][0]);
            acc[3][1] = fmaf(a.w, b.y, acc[3][1]);
            acc[3][2] = fmaf(a.w, b.z, acc[3][2]);
            acc[3][3] = fmaf(a.w, b.w, acc[3][3]);
        }
        __syncthreads();
    }

    const float4 bia = *(const float4*)(bias + col0 + (tx << 2));
    #pragma unroll
    for (int i = 0; i < 4; ++i) {
        float4 o;
        o.x = acc[i][0] + bia.x;
        o.y = acc[i][1] + bia.y;
        o.z = acc[i][2] + bia.z;
        o.w = acc[i][3] + bia.w;
        *(float4*)(C + (row0 + (ty << 2) + i) * N + col0 + (tx << 2)) = o;
    }
}

// ---------------------------------------------------------------------------
// Elementwise LIF scan over t, in place. buf is [T, M].
// ---------------------------------------------------------------------------
__global__ void k_lif_scan(float* __restrict__ buf, int M)
{
    const int j = blockIdx.x * blockDim.x + threadIdx.x;
    if (j >= M) return;
    float v = 0.0f;
    #pragma unroll
    for (int t = 0; t < T_STEPS; ++t) {
        const float xx = buf[t * M + j];
        v = fmaf(xx - v, 0.5f, v);
        const float s = (v >= 1.0f) ? 1.0f : 0.0f;
        buf[t * M + j] = s;
        v = (s != 0.0f) ? 0.0f : v;
    }
}

// ---------------------------------------------------------------------------
// Head: o[t,n] = h2[t,n,:] . W_out + b_out ; out[t,n] = cumsum_t o
// ---------------------------------------------------------------------------
__global__ void __launch_bounds__(256) k_head(
    const float* __restrict__ W_out, const float* __restrict__ b_out,
    float* __restrict__ out)
{
    const int n = blockIdx.x;
    const int g = threadIdx.x;
    const int lane = g & 31;
    const int warp = g >> 5;
    const float w  = W_out[g];
    const float bo = b_out[0];
    __shared__ float sh[T_STEPS][8];

    #pragma unroll 4
    for (int t = 0; t < T_STEPS; ++t) {
        float val = g_h2[(t * N_BATCH + n) * F2_DIM + g] * w;
        #pragma unroll
        for (int off = 16; off; off >>= 1)
            val += __shfl_down_sync(0xffffffffu, val, off);
        if (lane == 0) sh[t][warp] = val;
    }
    __syncthreads();
    if (warp == 0) {
        float z = bo;
        #pragma unroll
        for (int w8 = 0; w8 < 8; ++w8) z += sh[lane][w8];
        // sequential cumsum across lanes (lane == t)
        float acc = 0.0f, mine = 0.0f;
        #pragma unroll
        for (int t = 0; t < T_STEPS; ++t) {
            acc += __shfl_sync(0xffffffffu, z, t);
            if (lane == t) mine = acc;
        }
        out[lane * N_BATCH + n] = mine;
    }
}

extern "C" void kernel_launch(void* const* d_in, const int* in_sizes, int n_in,
                              void* d_out, int out_size)
{
    const float* x      = (const float*)d_in[0];
    const float* W_sdc  = (const float*)d_in[1];
    const float* b_sdc  = (const float*)d_in[2];
    const float* w_syn  = (const float*)d_in[3];
    const float* W_pool = (const float*)d_in[4];
    const float* b_pool = (const float*)d_in[5];
    const float* W_f1   = (const float*)d_in[6];
    const float* b_f1   = (const float*)d_in[7];
    const float* W_f2   = (const float*)d_in[8];
    const float* b_f2   = (const float*)d_in[9];
    const float* W_out  = (const float*)d_in[10];
    const float* b_out  = (const float*)d_in[11];
    float* out = (float*)d_out;

    float* s2 = nullptr; float* h1 = nullptr; float* h2 = nullptr;
    cudaGetSymbolAddress((void**)&s2, g_s2);
    cudaGetSymbolAddress((void**)&h1, g_h1);
    cudaGetSymbolAddress((void**)&h2, g_h2);

    // K1: fused SNN core -> g_s2 [T,N,D]
    k_snn_core<<<N_BATCH * D_DIM, 256>>>(x, W_sdc, b_sdc, w_syn, W_pool, b_pool);

    // K2: h1pre = s2 @ W_f1 + b_f1   (M=512, K=256, N=512)
    {
        dim3 grid(F1_DIM / 64, (T_STEPS * N_BATCH) / 32);
        k_gemm_bias<<<grid, 128>>>(s2, W_f1, b_f1, h1,
                                   T_STEPS * N_BATCH, D_DIM, F1_DIM);
    }
    // K3: LIF scan on h1, M = N*F1 = 8192
    k_lif_scan<<<(N_BATCH * F1_DIM) / 256, 256>>>(h1, N_BATCH * F1_DIM);

    // K4: h2pre = h1 @ W_f2 + b_f2   (M=512, K=512, N=256)
    {
        dim3 grid(F2_DIM / 64, (T_STEPS * N_BATCH) / 32);
        k_gemm_bias<<<grid, 128>>>(h1, W_f2, b_f2, h2,
                                   T_STEPS * N_BATCH, F1_DIM, F2_DIM);
    }
    // K5: LIF scan on h2, M = N*F2 = 4096
    k_lif_scan<<<(N_BATCH * F2_DIM) / 256, 256>>>(h2, N_BATCH * F2_DIM);

    // K6: readout dot + cumsum
    k_head<<<N_BATCH, 256>>>(W_out, b_out, out);
}